// round 4
// baseline (speedup 1.0000x reference)
#include <cuda_runtime.h>

// out[i] = |spherical[0]| * x[i] — HBM streaming at the roofline.
// 128e6 fp32 = 32e6 float4. Each thread: 4 front-batched LDG.128 (MLP=4),
// 32-bit indexing, streaming (.cs) cache hints for the touch-once data.

#define V_PER_THREAD 4

__global__ void __launch_bounds__(256) spherical_scale_kernel(
    const float4* __restrict__ x,
    const float* __restrict__ s,
    float4* __restrict__ out,
    unsigned int n4)
{
    const float a = fabsf(__ldg(s));
    unsigned int base = (blockIdx.x * blockDim.x + threadIdx.x) * V_PER_THREAD;

    if (base + V_PER_THREAD <= n4) {
        // Fast path: 4 independent loads issued back-to-back (front-batched MLP).
        float4 v0 = __ldcs(&x[base + 0]);
        float4 v1 = __ldcs(&x[base + 1]);
        float4 v2 = __ldcs(&x[base + 2]);
        float4 v3 = __ldcs(&x[base + 3]);

        v0.x *= a; v0.y *= a; v0.z *= a; v0.w *= a;
        v1.x *= a; v1.y *= a; v1.z *= a; v1.w *= a;
        v2.x *= a; v2.y *= a; v2.z *= a; v2.w *= a;
        v3.x *= a; v3.y *= a; v3.z *= a; v3.w *= a;

        __stcs(&out[base + 0], v0);
        __stcs(&out[base + 1], v1);
        __stcs(&out[base + 2], v2);
        __stcs(&out[base + 3], v3);
    } else {
        // Tail (not taken for 32e6 % 1024 == 0, but keep it correct generally).
        for (unsigned int i = base; i < n4; ++i) {
            float4 v = __ldcs(&x[i]);
            v.x *= a; v.y *= a; v.z *= a; v.w *= a;
            __stcs(&out[i], v);
        }
    }
}

extern "C" void kernel_launch(void* const* d_in, const int* in_sizes, int n_in,
                              void* d_out, int out_size)
{
    const float* x = (const float*)d_in[0];   // 1e6 x 128 fp32
    const float* s = (const float*)d_in[1];   // 1 fp32
    float* out = (float*)d_out;

    unsigned int n  = (unsigned int)in_sizes[0];  // 128,000,000
    unsigned int n4 = n >> 2;                     // 32,000,000 float4

    const int threads = 256;
    unsigned int per_block = threads * V_PER_THREAD;           // 1024 float4/CTA
    unsigned int blocks = (n4 + per_block - 1) / per_block;    // 31250

    spherical_scale_kernel<<<blocks, threads>>>(
        (const float4*)x, s, (float4*)out, n4);
}

// round 5
// speedup vs baseline: 1.0546x; 1.0546x over previous
#include <cuda_runtime.h>

// out[i] = |spherical[0]| * x[i] — HBM streaming.
// Coalesced-strided unroll: each CTA owns a contiguous 1024-float4 chunk;
// thread t handles chunk[t], chunk[t+256], chunk[t+512], chunk[t+768].
// Per LDG.128 instruction lane addresses are consecutive (fully dense
// 128B lines), while each thread still front-batches 4 independent loads
// (MLP_p1=4). Streaming cache hints: touch-once data.

#define THREADS 256
#define V_PER_THREAD 4
#define CHUNK (THREADS * V_PER_THREAD)   // 1024 float4 per CTA

__global__ void __launch_bounds__(THREADS) spherical_scale_kernel(
    const float4* __restrict__ x,
    const float* __restrict__ s,
    float4* __restrict__ out,
    unsigned int n4)
{
    const float a = fabsf(__ldg(s));
    const unsigned int chunk = blockIdx.x * CHUNK;
    const unsigned int t = threadIdx.x;

    if (chunk + CHUNK <= n4) {
        // Fast path: 4 coalesced, independent, front-batched LDG.128.
        float4 v0 = __ldcs(&x[chunk + t + 0 * THREADS]);
        float4 v1 = __ldcs(&x[chunk + t + 1 * THREADS]);
        float4 v2 = __ldcs(&x[chunk + t + 2 * THREADS]);
        float4 v3 = __ldcs(&x[chunk + t + 3 * THREADS]);

        v0.x *= a; v0.y *= a; v0.z *= a; v0.w *= a;
        v1.x *= a; v1.y *= a; v1.z *= a; v1.w *= a;
        v2.x *= a; v2.y *= a; v2.z *= a; v2.w *= a;
        v3.x *= a; v3.y *= a; v3.z *= a; v3.w *= a;

        __stcs(&out[chunk + t + 0 * THREADS], v0);
        __stcs(&out[chunk + t + 1 * THREADS], v1);
        __stcs(&out[chunk + t + 2 * THREADS], v2);
        __stcs(&out[chunk + t + 3 * THREADS], v3);
    } else {
        // Tail (never taken for n4 = 32e6, which is divisible by 1024).
        for (unsigned int i = chunk + t; i < n4; i += THREADS) {
            float4 v = __ldcs(&x[i]);
            v.x *= a; v.y *= a; v.z *= a; v.w *= a;
            __stcs(&out[i], v);
        }
    }
}

extern "C" void kernel_launch(void* const* d_in, const int* in_sizes, int n_in,
                              void* d_out, int out_size)
{
    const float* x = (const float*)d_in[0];   // 1e6 x 128 fp32
    const float* s = (const float*)d_in[1];   // 1 fp32
    float* out = (float*)d_out;

    unsigned int n  = (unsigned int)in_sizes[0];  // 128,000,000
    unsigned int n4 = n >> 2;                     // 32,000,000 float4

    unsigned int blocks = (n4 + CHUNK - 1) / CHUNK;   // 31250

    spherical_scale_kernel<<<blocks, THREADS>>>(
        (const float4*)x, s, (float4*)out, n4);
}